// round 1
// baseline (speedup 1.0000x reference)
#include <cuda_runtime.h>
#include <cstdint>

#define WINDOW 40
#define EE 8
#define NSTOCK 8000
#define TDIM 64
#define FDIM 64
#define INCH 144
#define LOUT 36

// rank scratch: [col][n], col = tw*8 + e, 320 columns
__device__ float g_rank[WINDOW * EE * NSTOCK];

// ---------------------------------------------------------------------------
// Kernel A: exact descending rank (stable, tie-break by index) per column.
// ---------------------------------------------------------------------------
#define NB 16384     // bins = top 14 bits of ordered key
#define RT 1024      // threads

__global__ void __launch_bounds__(RT) rank_kernel(const float* __restrict__ x) {
    extern __shared__ unsigned char smem_raw[];
    unsigned long long* g_pack = (unsigned long long*)smem_raw;            // 64000 B
    unsigned int* ofs  = (unsigned int*)(smem_raw + 64000);                // 65536 B
    unsigned int* hist = (unsigned int*)(smem_raw + 64000 + 65536);        // 65536 B
    float* rank_sm = (float*)hist;                                         // aliased after scatter

    __shared__ unsigned int wsum[32];

    const int col = blockIdx.x;
    const int tw  = col >> 3;
    const int e   = col & 7;
    const int tid = threadIdx.x;

    // zero hist
    for (int i = tid; i < NB; i += RT) hist[i] = 0u;
    __syncthreads();

    const float* base = x + (24 + tw) * FDIM + e;

    // pass 1: histogram
    for (int n = tid; n < NSTOCK; n += RT) {
        unsigned int u = __float_as_uint(__ldg(base + (size_t)n * (TDIM * FDIM)));
        u = (u & 0x80000000u) ? ~u : (u | 0x80000000u);
        atomicAdd(&hist[u >> 18], 1u);
    }
    __syncthreads();

    // block exclusive prefix sum over NB bins -> ofs
    {
        const int CH = NB / RT;              // 16 bins per thread
        const int b0 = tid * CH;
        unsigned int s = 0;
#pragma unroll
        for (int j = 0; j < CH; j++) {
            unsigned int h = hist[b0 + j];
            ofs[b0 + j] = s;
            s += h;
        }
        const unsigned int lane = tid & 31u;
        const unsigned int wid  = tid >> 5;
        unsigned int v = s;
#pragma unroll
        for (int o = 1; o < 32; o <<= 1) {
            unsigned int t = __shfl_up_sync(0xFFFFFFFFu, v, o);
            if (lane >= (unsigned)o) v += t;
        }
        if (lane == 31u) wsum[wid] = v;      // warp totals (inclusive of whole warp)
        __syncthreads();
        if (wid == 0) {
            unsigned int orig = wsum[lane];
            unsigned int w = orig;
#pragma unroll
            for (int o = 1; o < 32; o <<= 1) {
                unsigned int t = __shfl_up_sync(0xFFFFFFFFu, w, o);
                if (lane >= (unsigned)o) w += t;
            }
            wsum[lane] = w - orig;           // exclusive warp base
        }
        __syncthreads();
        const unsigned int tbase = wsum[wid] + (v - s);
#pragma unroll
        for (int j = 0; j < CH; j++) ofs[b0 + j] += tbase;
    }
    __syncthreads();

    // pass 2: scatter packed (key, inverted-index) grouped by bin
    for (int n = tid; n < NSTOCK; n += RT) {
        unsigned int u = __float_as_uint(__ldg(base + (size_t)n * (TDIM * FDIM)));
        u = (u & 0x80000000u) ? ~u : (u | 0x80000000u);
        unsigned int p = atomicAdd(&ofs[u >> 18], 1u);
        g_pack[p] = ((unsigned long long)u << 16) | (unsigned int)(65535 - n);
    }
    __syncthreads();
    // post-scatter: ofs[b] == end offset of bin b; start(b) = ofs[b-1]

    // pass 3: exact greater-count (tie-break encoded in pack ordering)
    for (int p = tid; p < NSTOCK; p += RT) {
        unsigned long long pk = g_pack[p];
        unsigned int b = (unsigned int)(pk >> 34);
        unsigned int end = ofs[b];
        unsigned int start = b ? ofs[b - 1] : 0u;
        unsigned int g = (unsigned int)NSTOCK - end;   // all elements in higher bins
        for (unsigned int q = start; q < end; q++)
            g += (g_pack[q] > pk) ? 1u : 0u;
        int idx = 65535 - (int)(pk & 0xFFFFull);
        rank_sm[idx] = (float)g * (1.0f / (float)NSTOCK);
    }
    __syncthreads();

    float* dst = g_rank + (size_t)col * NSTOCK;
    for (int n = tid; n < NSTOCK; n += RT) dst[n] = rank_sm[n];
}

// ---------------------------------------------------------------------------
// Kernel B: fused sliding-window stats + conv (only channel 127 matters) + linear
// ---------------------------------------------------------------------------
__global__ void __launch_bounds__(256) main_kernel(
    const float* __restrict__ x,
    const float* __restrict__ conv_w,
    const float* __restrict__ conv_b,
    const float* __restrict__ lin_w,
    const float* __restrict__ lin_b,
    float* __restrict__ out)
{
    __shared__ float xe[59][9];          // x[n, 5:64, 0:8], padded
    __shared__ float stats[WINDOW * 64]; // [tw][statid*8 + e], statid 0..7
    __shared__ float partial[5][LOUT];
    __shared__ float fin[LOUT];

    const int n = blockIdx.x;
    const int tid = threadIdx.x;
    const float* xn = x + (size_t)n * (TDIM * FDIM);

    // load xe = x[n, 5:64, 0:8]
    for (int i = tid; i < 59 * 8; i += 256) {
        int tt = i >> 3, e = i & 7;
        xe[tt][e] = __ldg(xn + (5 + tt) * FDIM + e);
    }
    __syncthreads();

    // stats: 320 (tw, e) tasks
    for (int i = tid; i < WINDOW * EE; i += 256) {
        int tw = i >> 3, e = i & 7;
        int te = 19 + tw;  // xe-row of window end (= t-5 of t=24+tw)

        // window-5
        float s5 = 0.f, mx5 = -1e30f, mn5 = 1e30f;
#pragma unroll
        for (int j = 0; j < 5; j++) {
            float v = xe[te - 4 + j][e];
            s5 += v; mx5 = fmaxf(mx5, v); mn5 = fminf(mn5, v);
        }
        float m5 = s5 * 0.2f;
        float var5 = 0.f;
#pragma unroll
        for (int j = 0; j < 5; j++) {
            float d = xe[te - 4 + j][e] - m5;
            var5 += d * d;
        }
        float sd5 = sqrtf(var5 * 0.25f);

        // window-20
        float s20 = 0.f, mx20 = -1e30f, mn20 = 1e30f;
#pragma unroll
        for (int j = 0; j < 20; j++) {
            float v = xe[te - 19 + j][e];
            s20 += v; mx20 = fmaxf(mx20, v); mn20 = fminf(mn20, v);
        }
        float m20 = s20 * 0.05f;
        float var20 = 0.f;
#pragma unroll
        for (int j = 0; j < 20; j++) {
            float d = xe[te - 19 + j][e] - m20;
            var20 += d * d;
        }
        float sd20 = sqrtf(var20 * (1.0f / 19.0f));

        float* st = stats + tw * 64 + e;
        st[0]  = m5;   st[8]  = sd5;  st[16] = mx5;  st[24] = mn5;
        st[32] = m20;  st[40] = sd20; st[48] = mx20; st[56] = mn20;
    }
    __syncthreads();

    // conv: thread tid < 144 owns input channel tid; 36 accumulators in regs
    float acc[LOUT];
#pragma unroll
    for (int l = 0; l < LOUT; l++) acc[l] = 0.f;

    const int c = tid;
    if (c < INCH) {
        const float* wp = conv_w + 127 * (INCH * 5) + c * 5;
        float w0 = __ldg(wp + 0), w1 = __ldg(wp + 1), w2 = __ldg(wp + 2),
              w3 = __ldg(wp + 3), w4 = __ldg(wp + 4);

        const float* src;
        long stride;
        if (c < FDIM) {                       // raw features
            src = xn + 24 * FDIM + c;
            stride = FDIM;
        } else {
            int cc = c - FDIM;
            int grp = (cc >= 40) ? 1 : 0;     // 0 = week, 1 = month
            int r = cc - grp * 40;
            int se = r >> 3;                  // 0 mean,1 std,2 rank,3 max,4 min
            int e = r & 7;
            if (se == 2) {                    // rank (same for week/month)
                src = g_rank + (size_t)e * NSTOCK + n;
                stride = 8 * NSTOCK;
            } else {
                int statid = (se < 2 ? se : se - 1) + grp * 4;
                src = (const float*)(stats + statid * 8 + e);
                stride = 64;
            }
        }

#pragma unroll
        for (int t = 0; t < WINDOW; t++) {
            float v = src[(long)t * stride];
#pragma unroll
            for (int k = 0; k < 5; k++) {
                int l = t - k;
                if (l >= 0 && l < LOUT) {
                    float wk = (k == 0) ? w0 : (k == 1) ? w1 : (k == 2) ? w2 : (k == 3) ? w3 : w4;
                    acc[l] += v * wk;
                }
            }
        }
    }

    // reduce across channel-owning warps (warps 0..4 cover tid 0..159)
    if (tid < 160) {
#pragma unroll
        for (int l = 0; l < LOUT; l++) {
            float a = acc[l];
#pragma unroll
            for (int o = 16; o > 0; o >>= 1)
                a += __shfl_xor_sync(0xFFFFFFFFu, a, o);
            if ((tid & 31) == 0) partial[tid >> 5][l] = a;
        }
    }
    __syncthreads();

    if (tid < LOUT) {
        float s = partial[0][tid] + partial[1][tid] + partial[2][tid] +
                  partial[3][tid] + partial[4][tid] + __ldg(conv_b + 127);
        float h = (s >= 0.f) ? s : 0.01f * s;
        fin[tid] = h * __ldg(lin_w + tid);
    }
    __syncthreads();

    if (tid == 0) {
        float s = __ldg(lin_b);
        for (int l = 0; l < LOUT; l++) s += fin[l];
        out[n] = s;
    }
}

// ---------------------------------------------------------------------------
extern "C" void kernel_launch(void* const* d_in, const int* in_sizes, int n_in,
                              void* d_out, int out_size) {
    const float* x      = (const float*)d_in[0];
    const float* conv_w = (const float*)d_in[1];
    const float* conv_b = (const float*)d_in[2];
    const float* lin_w  = (const float*)d_in[3];
    const float* lin_b  = (const float*)d_in[4];
    float* out = (float*)d_out;

    const size_t smemA = 64000 + 65536 + 65536;   // 195072 B
    cudaFuncSetAttribute(rank_kernel, cudaFuncAttributeMaxDynamicSharedMemorySize, (int)smemA);

    rank_kernel<<<WINDOW * EE, RT, smemA>>>(x);
    main_kernel<<<NSTOCK, 256>>>(x, conv_w, conv_b, lin_w, lin_b, out);
}